// round 3
// baseline (speedup 1.0000x reference)
#include <cuda_runtime.h>
#include <cstdint>

// Problem constants
#define B_  4
#define T_  4096
#define W_  1024
#define H_  8
#define BW_ 128

// GEMM tiling
#define BM 64
#define NTOT (B_*T_)                 // 16384 rows per head
#define MT_PER_BLOCK 4
#define GRIDX ((NTOT/BM)/MT_PER_BLOCK)   // 64

// Scan chunking
#define CH 64
#define NC (T_/CH)                   // 64

// Scratch (device globals: allocation inside kernel_launch is forbidden)
__device__ float g_a [(size_t)B_*T_*W_];   // decay a (0 at reset rows)
__device__ float g_nx[(size_t)B_*T_*W_];   // normed_x
__device__ float g_A [B_*NC*W_];           // per-chunk product of a
__device__ float g_H [B_*NC*W_];           // per-chunk local h end
__device__ float g_carry[B_*NC*W_];        // carry-in h per chunk

// ---------------- packed f32x2 helpers ----------------
__device__ __forceinline__ unsigned long long pack2(float v) {
    unsigned long long r;
    asm("mov.b64 %0, {%1, %1};" : "=l"(r) : "r"(__float_as_uint(v)));
    return r;
}
__device__ __forceinline__ void fma2(unsigned long long &d,
                                     unsigned long long a,
                                     unsigned long long b) {
    asm("fma.rn.f32x2 %0, %1, %2, %0;" : "+l"(d) : "l"(a), "l"(b));
}

// ---------------- K1: gates GEMM + pointwise ----------------
// Grid: (GRIDX, H). Block: 256 threads. One head per blockIdx.y.
// Combined weight matrix W_cat[k][n], n interleaved: n=2j -> w_in col j, n=2j+1 -> w_a col j.
// Thread (warp w, lane l) computes rows m0=w*8..+7, cols n0=l*8..+7 (=4 channel pairs).
__global__ __launch_bounds__(256, 1)
void gates_kernel(const float* __restrict__ x, const int* __restrict__ segp,
                  const float* __restrict__ a_param,
                  const float* __restrict__ w_in, const float* __restrict__ b_in,
                  const float* __restrict__ w_a,  const float* __restrict__ b_a)
{
    extern __shared__ float smem[];
    float* w_s    = smem;                   // [128][256]   128 KB
    float* x_s    = smem + 128*256;         // [64][128]    32 KB
    float* bias_s = x_s + 64*BW_;           // [256]
    float* c_s    = bias_s + 256;           // [128]  -8*softplus(a_param)

    const int tid = threadIdx.x;
    const int h   = blockIdx.y;

    {   // stage weights (interleaved), biases, decay constants
        const float* wi = w_in + h*BW_*BW_;
        const float* wa = w_a  + h*BW_*BW_;
        #pragma unroll 4
        for (int idx = tid; idx < BW_*BW_; idx += 256) {
            int k = idx >> 7, j = idx & 127;
            w_s[k*256 + 2*j]     = wi[idx];
            w_s[k*256 + 2*j + 1] = wa[idx];
        }
        if (tid < 128) {
            bias_s[2*tid]     = b_in[h*BW_ + tid];
            bias_s[2*tid + 1] = b_a [h*BW_ + tid];
            float ap = a_param[h*BW_ + tid];
            c_s[tid] = -8.0f * log1pf(__expf(ap));   // -8*softplus
        }
    }
    __syncthreads();

    const int warp = tid >> 5;
    const int lane = tid & 31;
    const int m0   = warp * 8;
    const int n0   = lane * 8;     // column base (0..248)
    const int ch0  = lane * 4;     // channel base within head (0..124)

    for (int tile = 0; tile < MT_PER_BLOCK; ++tile) {
        const int rbase = (blockIdx.x * MT_PER_BLOCK + tile) * BM;  // flat row b*T+t
        const float* xg = x + (size_t)rbase * W_ + h * BW_;

        // cooperative x tile load: [64][128], coalesced float4
        #pragma unroll
        for (int i = 0; i < 8; ++i) {
            int m = warp + i * 8;
            float4 v = *(const float4*)(xg + (size_t)m * W_ + lane * 4);
            *(float4*)(x_s + m * BW_ + lane * 4) = v;
        }
        __syncthreads();

        unsigned long long acc[32];
        #pragma unroll
        for (int i = 0; i < 32; ++i) acc[i] = 0ull;

        #pragma unroll 2
        for (int k = 0; k < BW_; k += 4) {
            float4 a4[8];   // x fragments for 4 k's, 8 m's (broadcast LDS.128)
            #pragma unroll
            for (int i = 0; i < 8; ++i)
                a4[i] = *(const float4*)(x_s + (m0 + i) * BW_ + k);
            #pragma unroll
            for (int kk = 0; kk < 4; ++kk) {
                const ulonglong2* bp = (const ulonglong2*)(w_s + (k + kk) * 256 + n0);
                ulonglong2 b01 = bp[0];
                ulonglong2 b23 = bp[1];
                #pragma unroll
                for (int i = 0; i < 8; ++i) {
                    float av = (kk == 0) ? a4[i].x : (kk == 1) ? a4[i].y
                             : (kk == 2) ? a4[i].z : a4[i].w;
                    unsigned long long ap2 = pack2(av);
                    fma2(acc[i*4+0], ap2, b01.x);
                    fma2(acc[i*4+1], ap2, b01.y);
                    fma2(acc[i*4+2], ap2, b23.x);
                    fma2(acc[i*4+3], ap2, b23.y);
                }
            }
        }

        // epilogue: sigmoid gates -> a, normed_x
        #pragma unroll
        for (int i = 0; i < 8; ++i) {
            const int m = m0 + i;
            const int r = rbase + m;
            const int reset = (segp[r] == 0);
            float4 xv4 = *(const float4*)(x_s + m * BW_ + ch0);
            float xa[4] = {xv4.x, xv4.y, xv4.z, xv4.w};
            float aout[4], nxout[4];
            #pragma unroll
            for (int c = 0; c < 4; ++c) {
                unsigned long long v = acc[i*4+c];
                float zx = __uint_as_float((unsigned)(v & 0xffffffffull)) + bias_s[n0 + 2*c];
                float za = __uint_as_float((unsigned)(v >> 32))           + bias_s[n0 + 2*c + 1];
                float gx = 1.0f / (1.0f + __expf(-zx));
                float ga = 1.0f / (1.0f + __expf(-za));
                float la = c_s[ch0 + c] * ga;          // log_a
                float a  = __expf(la);
                float mult = sqrtf(fmaxf(1.0f - a * a, 0.0f));
                nxout[c] = xa[c] * gx * mult;
                aout[c]  = reset ? 0.0f : a;
            }
            size_t o = (size_t)r * W_ + h * BW_ + ch0;
            *(float4*)(g_a  + o) = make_float4(aout[0],  aout[1],  aout[2],  aout[3]);
            *(float4*)(g_nx + o) = make_float4(nxout[0], nxout[1], nxout[2], nxout[3]);
        }
        __syncthreads();
    }
}

// ---------------- K2a: per-chunk scan summaries ----------------
__global__ void chunk_kernel()
{
    int gid  = blockIdx.x * blockDim.x + threadIdx.x;   // 0 .. B*NC*W-1
    int w    = gid & (W_ - 1);
    int rest = gid >> 10;
    int c    = rest & (NC - 1);
    int b    = rest >> 6;
    size_t base = ((size_t)(b * T_ + c * CH)) * W_ + w;
    float A = 1.0f, Hh = 0.0f;
    #pragma unroll 16
    for (int t = 0; t < CH; ++t) {
        float a  = g_a [base + (size_t)t * W_];
        float xv = g_nx[base + (size_t)t * W_];
        Hh = fmaf(a, Hh, xv);
        A *= a;
    }
    g_A[gid] = A;
    g_H[gid] = Hh;
}

// ---------------- K2b: scan over chunk summaries (carry-in per chunk) ----------------
__global__ void carry_kernel()
{
    int gid = blockIdx.x * blockDim.x + threadIdx.x;    // 0 .. B*W-1 (4096)
    int w   = gid & (W_ - 1);
    int b   = gid >> 10;
    float h = 0.0f;
    #pragma unroll 8
    for (int c = 0; c < NC; ++c) {
        int idx = ((b * NC + c) << 10) + w;
        g_carry[idx] = h;
        h = fmaf(g_A[idx], h, g_H[idx]);
    }
}

// ---------------- K3: replay chunks with carry, write output ----------------
__global__ void scan_kernel(float* __restrict__ out)
{
    int gid  = blockIdx.x * blockDim.x + threadIdx.x;   // 0 .. B*NC*W-1
    int w    = gid & (W_ - 1);
    int rest = gid >> 10;
    int c    = rest & (NC - 1);
    int b    = rest >> 6;
    size_t base = ((size_t)(b * T_ + c * CH)) * W_ + w;
    float h = g_carry[gid];
    #pragma unroll 16
    for (int t = 0; t < CH; ++t) {
        float a  = g_a [base + (size_t)t * W_];
        float xv = g_nx[base + (size_t)t * W_];
        h = fmaf(a, h, xv);
        out[base + (size_t)t * W_] = h;
    }
}

// ---------------- launch ----------------
extern "C" void kernel_launch(void* const* d_in, const int* in_sizes, int n_in,
                              void* d_out, int out_size)
{
    const float* x       = (const float*)d_in[0];
    const int*   segp    = (const int*)  d_in[1];
    const float* a_param = (const float*)d_in[2];
    const float* w_in    = (const float*)d_in[3];
    const float* b_in    = (const float*)d_in[4];
    const float* w_a     = (const float*)d_in[5];
    const float* b_a     = (const float*)d_in[6];
    float* out = (float*)d_out;

    const int smem_bytes = (128*256 + 64*BW_ + 256 + 128) * (int)sizeof(float); // 165376
    cudaFuncSetAttribute(gates_kernel,
                         cudaFuncAttributeMaxDynamicSharedMemorySize, smem_bytes);

    gates_kernel<<<dim3(GRIDX, H_), 256, smem_bytes>>>(x, segp, a_param,
                                                       w_in, b_in, w_a, b_a);
    chunk_kernel<<<(B_*NC*W_) / 256, 256>>>();
    carry_kernel<<<(B_*W_) / 256, 256>>>();
    scan_kernel <<<(B_*NC*W_) / 256, 256>>>(out);
}

// round 4
// speedup vs baseline: 1.3674x; 1.3674x over previous
#include <cuda_runtime.h>
#include <cstdint>

// Problem constants
#define B_  4
#define T_  4096
#define W_  1024
#define H_  8
#define BW_ 128

// GEMM tiling
#define BM 64
#define NTOT (B_*T_)                 // 16384 rows
#define MT_PER_BLOCK 2
#define GRIDX ((NTOT/BM)/MT_PER_BLOCK)   // 128 row-tiles per (head, half)

// Scan chunking
#define CH 64
#define NC (T_/CH)                   // 64

// Scratch (device globals: allocation inside kernel_launch is forbidden)
__device__ float g_a [(size_t)B_*T_*W_];   // decay a (0 at reset rows)
__device__ float g_nx[(size_t)B_*T_*W_];   // normed_x
__device__ float g_A [B_*NC*W_];           // per-chunk product of a
__device__ float g_H [B_*NC*W_];           // per-chunk local h end
__device__ float g_carry[B_*NC*W_];        // carry-in h per chunk

// ---------------- packed f32x2 helpers ----------------
__device__ __forceinline__ unsigned long long pack2(float v) {
    unsigned long long r;
    asm("mov.b64 %0, {%1, %1};" : "=l"(r) : "r"(__float_as_uint(v)));
    return r;
}
__device__ __forceinline__ void fma2(unsigned long long &d,
                                     unsigned long long a,
                                     unsigned long long b) {
    asm("fma.rn.f32x2 %0, %1, %2, %0;" : "+l"(d) : "l"(a), "l"(b));
}
__device__ __forceinline__ float fast_tanh(float x) {
    float r;
    asm("tanh.approx.f32 %0, %1;" : "=f"(r) : "f"(x));
    return r;
}
__device__ __forceinline__ float fast_sigmoid(float x) {
    return fmaf(fast_tanh(0.5f * x), 0.5f, 0.5f);
}

// ---------------- K1: gates GEMM + pointwise ----------------
// Grid: (GRIDX, H, 2). blockIdx.z = column half (64 channels each).
// Weight smem layout per half: w_s[k][ln], ln = 2*jl + gate  (jl in [0,64)).
// Thread (warp w, lane l): rows m0=w*8..+7, local cols 4l..4l+3
//   = channels jl = 2l, 2l+1 (each with both gates adjacent -> one f32x2 each).
// Per k: ONE conflict-free LDS.128 (lanes at 16B stride over 512B row).
__global__ __launch_bounds__(256, 2)
void gates_kernel(const float* __restrict__ x, const int* __restrict__ segp,
                  const float* __restrict__ a_param,
                  const float* __restrict__ w_in, const float* __restrict__ b_in,
                  const float* __restrict__ w_a,  const float* __restrict__ b_a)
{
    extern __shared__ float smem[];
    float* w_s    = smem;                    // [128][128]  64 KB
    float* x_s    = smem + 128*128;          // [64][128]   32 KB
    float* bias_s = x_s + 64*BW_;            // [128]
    float* c_s    = bias_s + 128;            // [64]

    const int tid = threadIdx.x;
    const int h   = blockIdx.y;
    const int z   = blockIdx.z;              // column half

    {   // stage weights for this half (interleaved per-channel gate pairs)
        const float* wi = w_in + h*BW_*BW_;
        const float* wa = w_a  + h*BW_*BW_;
        #pragma unroll 4
        for (int idx = tid; idx < 128*128; idx += 256) {
            int k  = idx >> 7;
            int ln = idx & 127;
            int j  = z*64 + (ln >> 1);
            const float* src = (ln & 1) ? wa : wi;
            w_s[idx] = src[k*BW_ + j];
        }
        if (tid < 128) {
            int j = z*64 + (tid >> 1);
            bias_s[tid] = (tid & 1) ? b_a[h*BW_ + j] : b_in[h*BW_ + j];
        }
        if (tid < 64) {
            float ap = a_param[h*BW_ + z*64 + tid];
            c_s[tid] = -8.0f * log1pf(__expf(ap));   // -8*softplus
        }
    }
    __syncthreads();

    const int warp = tid >> 5;
    const int lane = tid & 31;
    const int m0   = warp * 8;

    for (int tile = 0; tile < MT_PER_BLOCK; ++tile) {
        const int rbase = (blockIdx.x * MT_PER_BLOCK + tile) * BM;
        const float* xg = x + (size_t)rbase * W_ + h * BW_;

        // cooperative x tile load: [64][128] floats, coalesced float4
        #pragma unroll
        for (int i = 0; i < 8; ++i) {
            int m = warp + i * 8;
            float4 v = *(const float4*)(xg + (size_t)m * W_ + lane * 4);
            *(float4*)(x_s + m * BW_ + lane * 4) = v;
        }
        __syncthreads();

        unsigned long long acc[16];   // 8 rows x 2 f32x2 (= 2 channels)
        #pragma unroll
        for (int i = 0; i < 16; ++i) acc[i] = 0ull;

        #pragma unroll 2
        for (int k = 0; k < BW_; k += 4) {
            float4 a4[8];   // x frags: 4 k's x 8 rows (broadcast LDS.128)
            #pragma unroll
            for (int i = 0; i < 8; ++i)
                a4[i] = *(const float4*)(x_s + (m0 + i) * BW_ + k);
            #pragma unroll
            for (int kk = 0; kk < 4; ++kk) {
                ulonglong2 b = *(const ulonglong2*)(w_s + (k + kk) * 128 + lane * 4);
                #pragma unroll
                for (int i = 0; i < 8; ++i) {
                    float av = (kk == 0) ? a4[i].x : (kk == 1) ? a4[i].y
                             : (kk == 2) ? a4[i].z : a4[i].w;
                    unsigned long long ap2 = pack2(av);
                    fma2(acc[i*2+0], ap2, b.x);
                    fma2(acc[i*2+1], ap2, b.y);
                }
            }
        }

        // epilogue: sigmoid gates -> a, normed_x   (2 channels per thread-row)
        const int ch = z*64 + 2*lane;             // channel within head
        #pragma unroll
        for (int i = 0; i < 8; ++i) {
            const int m = m0 + i;
            const int r = rbase + m;
            const int reset = (segp[r] == 0);
            float2 xv = *(const float2*)(x_s + m * BW_ + ch);
            float xa[2] = {xv.x, xv.y};
            float aout[2], nxout[2];
            #pragma unroll
            for (int c = 0; c < 2; ++c) {
                unsigned long long v = acc[i*2+c];
                float zx = __uint_as_float((unsigned)(v & 0xffffffffull)) + bias_s[4*lane + 2*c];
                float za = __uint_as_float((unsigned)(v >> 32))           + bias_s[4*lane + 2*c + 1];
                float gx = fast_sigmoid(zx);
                float ga = fast_sigmoid(za);
                float la = c_s[2*lane + c] * ga;          // log_a
                float a  = __expf(la);
                float mult = sqrtf(fmaxf(1.0f - a * a, 0.0f));
                nxout[c] = xa[c] * gx * mult;
                aout[c]  = reset ? 0.0f : a;
            }
            size_t o = (size_t)r * W_ + h * BW_ + ch;
            *(float2*)(g_a  + o) = make_float2(aout[0],  aout[1]);
            *(float2*)(g_nx + o) = make_float2(nxout[0], nxout[1]);
        }
        __syncthreads();
    }
}

// ---------------- K2a: per-chunk scan summaries ----------------
__global__ void chunk_kernel()
{
    int gid  = blockIdx.x * blockDim.x + threadIdx.x;   // 0 .. B*NC*W-1
    int w    = gid & (W_ - 1);
    int rest = gid >> 10;
    int c    = rest & (NC - 1);
    int b    = rest >> 6;
    size_t base = ((size_t)(b * T_ + c * CH)) * W_ + w;
    float A = 1.0f, Hh = 0.0f;
    #pragma unroll 16
    for (int t = 0; t < CH; ++t) {
        float a  = g_a [base + (size_t)t * W_];
        float xv = g_nx[base + (size_t)t * W_];
        Hh = fmaf(a, Hh, xv);
        A *= a;
    }
    g_A[gid] = A;
    g_H[gid] = Hh;
}

// ---------------- K2b: scan over chunk summaries ----------------
__global__ void carry_kernel()
{
    int gid = blockIdx.x * blockDim.x + threadIdx.x;    // 0 .. B*W-1 (4096)
    int w   = gid & (W_ - 1);
    int b   = gid >> 10;
    float h = 0.0f;
    #pragma unroll 8
    for (int c = 0; c < NC; ++c) {
        int idx = ((b * NC + c) << 10) + w;
        g_carry[idx] = h;
        h = fmaf(g_A[idx], h, g_H[idx]);
    }
}

// ---------------- K3: replay chunks with carry, write output ----------------
__global__ void scan_kernel(float* __restrict__ out)
{
    int gid  = blockIdx.x * blockDim.x + threadIdx.x;   // 0 .. B*NC*W-1
    int w    = gid & (W_ - 1);
    int rest = gid >> 10;
    int c    = rest & (NC - 1);
    int b    = rest >> 6;
    size_t base = ((size_t)(b * T_ + c * CH)) * W_ + w;
    float h = g_carry[gid];
    #pragma unroll 16
    for (int t = 0; t < CH; ++t) {
        float a  = g_a [base + (size_t)t * W_];
        float xv = g_nx[base + (size_t)t * W_];
        h = fmaf(a, h, xv);
        out[base + (size_t)t * W_] = h;
    }
}

// ---------------- launch ----------------
extern "C" void kernel_launch(void* const* d_in, const int* in_sizes, int n_in,
                              void* d_out, int out_size)
{
    const float* x       = (const float*)d_in[0];
    const int*   segp    = (const int*)  d_in[1];
    const float* a_param = (const float*)d_in[2];
    const float* w_in    = (const float*)d_in[3];
    const float* b_in    = (const float*)d_in[4];
    const float* w_a     = (const float*)d_in[5];
    const float* b_a     = (const float*)d_in[6];
    float* out = (float*)d_out;

    const int smem_bytes = (128*128 + 64*BW_ + 128 + 64) * (int)sizeof(float); // 99072
    cudaFuncSetAttribute(gates_kernel,
                         cudaFuncAttributeMaxDynamicSharedMemorySize, smem_bytes);

    gates_kernel<<<dim3(GRIDX, H_, 2), 256, smem_bytes>>>(x, segp, a_param,
                                                          w_in, b_in, w_a, b_a);
    chunk_kernel<<<(B_*NC*W_) / 256, 256>>>();
    carry_kernel<<<(B_*W_) / 256, 256>>>();
    scan_kernel <<<(B_*NC*W_) / 256, 256>>>(out);
}

// round 5
// speedup vs baseline: 1.6356x; 1.1961x over previous
#include <cuda_runtime.h>
#include <cstdint>

// Problem constants
#define B_  4
#define T_  4096
#define W_  1024
#define H_  8
#define BW_ 128

// GEMM tiling
#define BM 64
#define BN 256                       // 128 channels x 2 gates, interleaved
#define MT 2
#define GRIDX (B_*T_/BM/MT)          // 128 row-tile groups

#define WS 264                       // w_s row stride (floats): bank (8k+n)%32 conflict-free
#define XS 132                       // x_s row stride (floats): bank (4r+k)%32 conflict-free

// Scan chunking
#define CH 64
#define NC (T_/CH)                   // 64

// Scratch (device globals: allocation inside kernel_launch is forbidden)
__device__ float2 g_anx [(size_t)B_*T_*W_];  // (a, normed_x) interleaved
__device__ float  g_A   [B_*NC*W_];
__device__ float  g_H   [B_*NC*W_];
__device__ float  g_carry[B_*NC*W_];

// ---------------- helpers ----------------
__device__ __forceinline__ uint32_t f2tf32(float f) {
    uint32_t r; asm("cvt.rna.tf32.f32 %0, %1;" : "=r"(r) : "f"(f)); return r;
}
__device__ __forceinline__ void mma_tf32(float4 &d, const uint32_t a[4],
                                         uint32_t b0, uint32_t b1) {
    asm("mma.sync.aligned.m16n8k8.row.col.f32.tf32.tf32.f32 "
        "{%0,%1,%2,%3}, {%4,%5,%6,%7}, {%8,%9}, {%0,%1,%2,%3};"
        : "+f"(d.x), "+f"(d.y), "+f"(d.z), "+f"(d.w)
        : "r"(a[0]), "r"(a[1]), "r"(a[2]), "r"(a[3]), "r"(b0), "r"(b1));
}
__device__ __forceinline__ float fast_tanh(float x) {
    float r; asm("tanh.approx.f32 %0, %1;" : "=f"(r) : "f"(x)); return r;
}
__device__ __forceinline__ float fast_sigmoid(float x) {
    return fmaf(fast_tanh(0.5f * x), 0.5f, 0.5f);
}

// ---------------- K1: gates GEMM (tf32 tensor cores) + pointwise ----------------
// Grid (GRIDX, H). Block 256 thr = 8 warps in 2x4 grid:
//   warp row wm = (warp>>2)*32 (2 m-frags of 16), warp col wn = (warp&3)*64 (8 n-frags of 8).
// n = 2*ch + gate, so each mma C pair (c0,c1)/(c2,c3) = (zx,za) of one channel.
__global__ __launch_bounds__(256, 1)
void gates_kernel(const float* __restrict__ x, const int* __restrict__ segp,
                  const float* __restrict__ a_param,
                  const float* __restrict__ w_in, const float* __restrict__ b_in,
                  const float* __restrict__ w_a,  const float* __restrict__ b_a)
{
    extern __shared__ float smem[];
    float* w_s    = smem;                    // [128][WS]  tf32 bits
    float* x_s    = smem + 128*WS;           // [64][XS]   fp32
    float* bias_s = x_s + 64*XS;             // [256]
    float* c_s    = bias_s + 256;            // [128] : -8*softplus(a_param)
    int*   seg_s  = (int*)(c_s + 128);       // [64]

    const int tid = threadIdx.x;
    const int h   = blockIdx.y;

    {   // stage weights (tf32-converted, interleaved), biases, decay consts
        const float* wi = w_in + h*BW_*BW_;
        const float* wa = w_a  + h*BW_*BW_;
        #pragma unroll 4
        for (int idx = tid; idx < 128*BN; idx += 256) {
            int k = idx >> 8, n = idx & 255;
            int ch = n >> 1;
            float v = (n & 1) ? wa[k*BW_ + ch] : wi[k*BW_ + ch];
            w_s[k*WS + n] = __uint_as_float(f2tf32(v));
        }
        if (tid < 256)
            bias_s[tid] = (tid & 1) ? b_a[h*BW_ + (tid>>1)] : b_in[h*BW_ + (tid>>1)];
        if (tid < 128) {
            float ap = a_param[h*BW_ + tid];
            c_s[tid] = -8.0f * log1pf(__expf(ap));
        }
    }

    const int warp = tid >> 5, lane = tid & 31;
    const int wm = (warp >> 2) * 32;
    const int wn = (warp & 3) * 64;
    const int lr = lane >> 2;     // 0..7
    const int lc = lane & 3;      // 0..3

    for (int tile = 0; tile < MT; ++tile) {
        const int rbase = (blockIdx.x * MT + tile) * BM;
        __syncthreads();   // weights ready (tile 0) / x_s no longer read (tile 1)

        {   // stage x tile [64][128] fp32, coalesced float4
            const float* xg = x + (size_t)rbase * W_ + h * BW_;
            #pragma unroll
            for (int idx = tid; idx < 64*32; idx += 256) {
                int m = idx >> 5, c4 = idx & 31;
                float4 v = *(const float4*)(xg + (size_t)m * W_ + c4*4);
                *(float4*)(x_s + m*XS + c4*4) = v;
            }
            if (tid < 64) seg_s[tid] = segp[rbase + tid];
        }
        __syncthreads();

        float4 acc[2][8];
        #pragma unroll
        for (int mf = 0; mf < 2; ++mf)
            #pragma unroll
            for (int nf = 0; nf < 8; ++nf)
                acc[mf][nf] = make_float4(0.f, 0.f, 0.f, 0.f);

        #pragma unroll
        for (int ks = 0; ks < 16; ++ks) {
            const int k0 = ks * 8;
            uint32_t a[2][4];
            #pragma unroll
            for (int mf = 0; mf < 2; ++mf) {
                const float* xr = x_s + (wm + mf*16 + lr)*XS + k0 + lc;
                a[mf][0] = f2tf32(xr[0]);
                a[mf][1] = f2tf32(xr[8*XS]);
                a[mf][2] = f2tf32(xr[4]);
                a[mf][3] = f2tf32(xr[8*XS + 4]);
            }
            #pragma unroll
            for (int nf = 0; nf < 8; ++nf) {
                const float* wp = w_s + (k0 + lc)*WS + wn + nf*8 + lr;
                uint32_t b0 = __float_as_uint(wp[0]);
                uint32_t b1 = __float_as_uint(wp[4*WS]);
                mma_tf32(acc[0][nf], a[0], b0, b1);
                mma_tf32(acc[1][nf], a[1], b0, b1);
            }
        }

        // epilogue
        #pragma unroll
        for (int mf = 0; mf < 2; ++mf) {
            const int r0 = wm + mf*16 + lr;
            #pragma unroll
            for (int nf = 0; nf < 8; ++nf) {
                const int chl = (wn >> 1) + nf*4 + lc;     // channel 0..127
                const float bx = bias_s[2*chl];
                const float ba = bias_s[2*chl + 1];
                const float cc = c_s[chl];
                #pragma unroll
                for (int half = 0; half < 2; ++half) {
                    const int r  = r0 + half*8;
                    const float zx = (half ? acc[mf][nf].z : acc[mf][nf].x) + bx;
                    const float za = (half ? acc[mf][nf].w : acc[mf][nf].y) + ba;
                    const float gx = fast_sigmoid(zx);
                    const float ga = fast_sigmoid(za);
                    const float la = cc * ga;
                    const float av = __expf(la);
                    const float mult = sqrtf(fmaxf(1.0f - av*av, 0.0f));
                    const float xv = x_s[r*XS + chl];
                    const float nx = xv * gx * mult;
                    const float ao = (seg_s[r] == 0) ? 0.0f : av;
                    g_anx[(size_t)(rbase + r) * W_ + h*BW_ + chl] = make_float2(ao, nx);
                }
            }
        }
    }
}

// ---------------- K2a: per-chunk scan summaries ----------------
__global__ void chunk_kernel()
{
    int gid  = blockIdx.x * blockDim.x + threadIdx.x;   // 0 .. B*NC*W-1
    int w    = gid & (W_ - 1);
    int rest = gid >> 10;
    int c    = rest & (NC - 1);
    int b    = rest >> 6;
    size_t base = ((size_t)(b * T_ + c * CH)) * W_ + w;
    float A = 1.0f, Hh = 0.0f;
    #pragma unroll 16
    for (int t = 0; t < CH; ++t) {
        float2 v = g_anx[base + (size_t)t * W_];
        Hh = fmaf(v.x, Hh, v.y);
        A *= v.x;
    }
    g_A[gid] = A;
    g_H[gid] = Hh;
}

// ---------------- K2b: scan over chunk summaries ----------------
__global__ void carry_kernel()
{
    int gid = blockIdx.x * blockDim.x + threadIdx.x;    // 0 .. B*W-1 (4096)
    int w   = gid & (W_ - 1);
    int b   = gid >> 10;
    float h = 0.0f;
    #pragma unroll 8
    for (int c = 0; c < NC; ++c) {
        int idx = ((b * NC + c) << 10) + w;
        g_carry[idx] = h;
        h = fmaf(g_A[idx], h, g_H[idx]);
    }
}

// ---------------- K3: replay chunks with carry, write output ----------------
__global__ void scan_kernel(float* __restrict__ out)
{
    int gid  = blockIdx.x * blockDim.x + threadIdx.x;   // 0 .. B*NC*W-1
    int w    = gid & (W_ - 1);
    int rest = gid >> 10;
    int c    = rest & (NC - 1);
    int b    = rest >> 6;
    size_t base = ((size_t)(b * T_ + c * CH)) * W_ + w;
    float h = g_carry[gid];
    #pragma unroll 16
    for (int t = 0; t < CH; ++t) {
        float2 v = g_anx[base + (size_t)t * W_];
        h = fmaf(v.x, h, v.y);
        out[base + (size_t)t * W_] = h;
    }
}

// ---------------- launch ----------------
extern "C" void kernel_launch(void* const* d_in, const int* in_sizes, int n_in,
                              void* d_out, int out_size)
{
    const float* x       = (const float*)d_in[0];
    const int*   segp    = (const int*)  d_in[1];
    const float* a_param = (const float*)d_in[2];
    const float* w_in    = (const float*)d_in[3];
    const float* b_in    = (const float*)d_in[4];
    const float* w_a     = (const float*)d_in[5];
    const float* b_a     = (const float*)d_in[6];
    float* out = (float*)d_out;

    const int smem_bytes = (128*WS + 64*XS + 256 + 128 + 64) * (int)sizeof(float); // 170752
    cudaFuncSetAttribute(gates_kernel,
                         cudaFuncAttributeMaxDynamicSharedMemorySize, smem_bytes);

    gates_kernel<<<dim3(GRIDX, H_), 256, smem_bytes>>>(x, segp, a_param,
                                                       w_in, b_in, w_a, b_a);
    chunk_kernel<<<(B_*NC*W_) / 256, 256>>>();
    carry_kernel<<<(B_*W_) / 256, 256>>>();
    scan_kernel <<<(B_*NC*W_) / 256, 256>>>(out);
}

// round 8
// speedup vs baseline: 1.7094x; 1.0451x over previous
#include <cuda_runtime.h>
#include <cstdint>

// Problem constants
#define B_  4
#define T_  4096
#define W_  1024
#define H_  8

// GEMM tiling: per block BM=64 rows x BN=128 (64 ch x 2 gates) x K=128
#define BM 64
#define MT 2
#define GRIDX (B_*T_/BM/MT)          // 128 -> grid (128, 8, 2) = 2048 blocks

#define WS 136   // w_s row stride (floats), 136%32=8 : B-frag bank = 8*lc+lr, conflict-free
#define XS 132   // x_s row stride (floats), 132%32=4 : A-frag bank = 4*lr+lc, conflict-free

// Scan chunking: 32 chunks of 128 steps, decoupled lookback
#define CL 128
#define NCH (T_/CL)                  // 32

// Scratch (no allocations allowed)
__device__ float2 g_anx[(size_t)B_*T_*W_];      // (a, normed_x)
__device__ float2 g_agg[B_*NCH*W_];             // per-chunk (A, H)
__device__ int    g_flag[B_*NCH];               // chunk-published flags

// ---------------- helpers ----------------
__device__ __forceinline__ uint32_t f2tf32(float f) {
    uint32_t r; asm("cvt.rna.tf32.f32 %0, %1;" : "=r"(r) : "f"(f)); return r;
}
__device__ __forceinline__ void mma_tf32(float4 &d, const uint32_t a[4],
                                         uint32_t b0, uint32_t b1) {
    asm("mma.sync.aligned.m16n8k8.row.col.f32.tf32.tf32.f32 "
        "{%0,%1,%2,%3}, {%4,%5,%6,%7}, {%8,%9}, {%0,%1,%2,%3};"
        : "+f"(d.x), "+f"(d.y), "+f"(d.z), "+f"(d.w)
        : "r"(a[0]), "r"(a[1]), "r"(a[2]), "r"(a[3]), "r"(b0), "r"(b1));
}
__device__ __forceinline__ float fast_tanh(float x) {
    float r; asm("tanh.approx.f32 %0, %1;" : "=f"(r) : "f"(x)); return r;
}
__device__ __forceinline__ float fast_sigmoid(float x) {
    return fmaf(fast_tanh(0.5f * x), 0.5f, 0.5f);
}
__device__ __forceinline__ float fast_sqrt(float x) {
    float r; asm("sqrt.approx.f32 %0, %1;" : "=f"(r) : "f"(x)); return r;
}

// ---------------- K1: gates GEMM (tf32 mma, occ 2) + pointwise ----------------
// Grid (GRIDX, H, 2). Block 256 thr = 8 warps in 2x4:
//   wm = (warp>>2)*32 (2 m-frags of 16), wn = (warp&3)*32 (4 n-frags of 8).
// Local n = 2*chl + gate (chl in [0,64)), global ch = z*64 + chl.
__global__ __launch_bounds__(256, 2)
void gates_kernel(const float* __restrict__ x, const int* __restrict__ segp,
                  const float* __restrict__ a_param,
                  const float* __restrict__ w_in, const float* __restrict__ b_in,
                  const float* __restrict__ w_a,  const float* __restrict__ b_a)
{
    extern __shared__ float smem[];
    float* w_s    = smem;                    // [128][WS] tf32 bits   69632 B
    float* x_s    = smem + 128*WS;           // [64][XS]  tf32 bits   33792 B
    float* bias_s = x_s + 64*XS;             // [128]
    float* c_s    = bias_s + 128;            // [64]
    int*   seg_s  = (int*)(c_s + 64);        // [2][64]

    const int tid = threadIdx.x;
    const int h   = blockIdx.y;
    const int z   = blockIdx.z;

    {   // stage weights (tf32), biases, decay consts for this column half
        const float* wi = w_in + h*128*128;
        const float* wa = w_a  + h*128*128;
        #pragma unroll 4
        for (int i = tid; i < 128*128; i += 256) {
            int k = i >> 7, n = i & 127;
            int ch = z*64 + (n >> 1);
            float v = (n & 1) ? wa[k*128 + ch] : wi[k*128 + ch];
            w_s[k*WS + n] = __uint_as_float(f2tf32(v));
        }
        if (tid < 128)
            bias_s[tid] = (tid & 1) ? b_a[h*128 + z*64 + (tid>>1)]
                                    : b_in[h*128 + z*64 + (tid>>1)];
        if (tid < 64)
            c_s[tid] = -8.0f * log1pf(__expf(a_param[h*128 + z*64 + tid]));
    }

    const int warp = tid >> 5, lane = tid & 31;
    const int wm = (warp >> 2) * 32;
    const int wn = (warp & 3) * 32;
    const int lr = lane >> 2;     // 0..7
    const int lc = lane & 3;      // 0..3

    auto stage_x = [&](int tt) {
        const int rbase = (blockIdx.x * MT + tt) * BM;
        const float* xg = x + (size_t)rbase * W_ + h * 128;
        #pragma unroll
        for (int i = tid; i < 64*32; i += 256) {
            int m = i >> 5, c4 = i & 31;
            float4 v = *(const float4*)(xg + (size_t)m * W_ + c4*4);
            float4 o;
            o.x = __uint_as_float(f2tf32(v.x));
            o.y = __uint_as_float(f2tf32(v.y));
            o.z = __uint_as_float(f2tf32(v.z));
            o.w = __uint_as_float(f2tf32(v.w));
            *(float4*)(x_s + m*XS + c4*4) = o;
        }
        if (tid < 64) seg_s[(tt & 1)*64 + tid] = segp[rbase + tid];
    };

    stage_x(0);

    for (int t = 0; t < MT; ++t) {
        __syncthreads();    // weights/x_s stores visible

        float4 acc[2][4];
        #pragma unroll
        for (int mf = 0; mf < 2; ++mf)
            #pragma unroll
            for (int nf = 0; nf < 4; ++nf)
                acc[mf][nf] = make_float4(0.f, 0.f, 0.f, 0.f);

        #pragma unroll
        for (int ks = 0; ks < 16; ++ks) {
            const int k0 = ks * 8;
            uint32_t a[2][4];
            #pragma unroll
            for (int mf = 0; mf < 2; ++mf) {
                const float* xr = x_s + (wm + mf*16 + lr)*XS + k0 + lc;
                a[mf][0] = __float_as_uint(xr[0]);
                a[mf][1] = __float_as_uint(xr[8*XS]);
                a[mf][2] = __float_as_uint(xr[4]);
                a[mf][3] = __float_as_uint(xr[8*XS + 4]);
            }
            #pragma unroll
            for (int nf = 0; nf < 4; ++nf) {
                const float* wp = w_s + (k0 + lc)*WS + wn + nf*8 + lr;
                uint32_t b0 = __float_as_uint(wp[0]);
                uint32_t b1 = __float_as_uint(wp[4*WS]);
                mma_tf32(acc[0][nf], a[0], b0, b1);
                mma_tf32(acc[1][nf], a[1], b0, b1);
            }
        }
        __syncthreads();    // x_s reads done

        if (t + 1 < MT) stage_x(t + 1);   // overlaps epilogue below

        // ---- epilogue for tile t ----
        const int rbase = (blockIdx.x * MT + t) * BM;
        #pragma unroll
        for (int mf = 0; mf < 2; ++mf) {
            #pragma unroll
            for (int nf = 0; nf < 4; ++nf) {
                const int chl = (wn >> 1) + nf*4 + lc;     // 0..63
                const int ch  = z*64 + chl;                // 0..127
                const float bx = bias_s[2*chl];
                const float ba = bias_s[2*chl + 1];
                const float cc = c_s[chl];
                #pragma unroll
                for (int half = 0; half < 2; ++half) {
                    const int r   = wm + mf*16 + lr + half*8;
                    const int row = rbase + r;
                    const float zx = (half ? acc[mf][nf].z : acc[mf][nf].x) + bx;
                    const float za = (half ? acc[mf][nf].w : acc[mf][nf].y) + ba;
                    const float gx = fast_sigmoid(zx);
                    const float ga = fast_sigmoid(za);
                    const float la = cc * ga;
                    const float av = __expf(la);
                    const float mult = fast_sqrt(fmaxf(1.0f - av*av, 0.0f));
                    const float xv = __ldg(x + (size_t)row * W_ + h*128 + ch);
                    const float nx = xv * gx * mult;
                    const float ao = (seg_s[(t & 1)*64 + r] == 0) ? 0.0f : av;
                    g_anx[(size_t)row * W_ + h*128 + ch] = make_float2(ao, nx);
                }
            }
        }
    }
}

// ---------------- flag clear (graph-replay determinism) ----------------
__global__ void clear_flags()
{
    if (threadIdx.x < B_*NCH) g_flag[threadIdx.x] = 0;
}

// ---------------- K2: fused scan with decoupled lookback ----------------
// Grid (W/256=4, NCH=32, B=4) = 512 blocks, all co-resident -> spin is safe.
__global__ __launch_bounds__(256, 4)
void fused_scan(float* __restrict__ out)
{
    const int w = blockIdx.x * 256 + threadIdx.x;
    const int c = blockIdx.y;
    const int b = blockIdx.z;
    const size_t base = ((size_t)(b * T_ + c * CL)) * W_ + w;

    // phase 1: local chunk summary
    float A = 1.0f, Hl = 0.0f;
    #pragma unroll 8
    for (int t = 0; t < CL; ++t) {
        float2 v = g_anx[base + (size_t)t * W_];
        Hl = fmaf(v.x, Hl, v.y);
        A *= v.x;
    }
    g_agg[(size_t)(b*NCH + c) * W_ + w] = make_float2(A, Hl);
    __threadfence();
    __syncthreads();
    if (threadIdx.x == 0)
        atomicExch(&g_flag[b*NCH + c], 1);     // publish after fence

    // phase 2: lookback — compose all predecessor aggregates
    float carry = 0.0f;
    if (c > 0) {
        if (threadIdx.x == 0) {
            #pragma unroll 1
            for (int k = 0; k < c; ++k) {
                volatile int* f = &g_flag[b*NCH + k];
                while (*f == 0) { }
            }
        }
        __syncthreads();
        __threadfence();
        const float2* ag = g_agg + (size_t)(b*NCH) * W_ + w;
        #pragma unroll 4
        for (int k = 0; k < c; ++k) {
            float2 g = ag[(size_t)k * W_];
            carry = fmaf(g.x, carry, g.y);
        }
    }

    // phase 3: replay with carry, write output
    float h = carry;
    #pragma unroll 8
    for (int t = 0; t < CL; ++t) {
        float2 v = g_anx[base + (size_t)t * W_];
        h = fmaf(v.x, h, v.y);
        out[base + (size_t)t * W_] = h;
    }
}

// ---------------- launch ----------------
extern "C" void kernel_launch(void* const* d_in, const int* in_sizes, int n_in,
                              void* d_out, int out_size)
{
    const float* x       = (const float*)d_in[0];
    const int*   segp    = (const int*)  d_in[1];
    const float* a_param = (const float*)d_in[2];
    const float* w_in    = (const float*)d_in[3];
    const float* b_in    = (const float*)d_in[4];
    const float* w_a     = (const float*)d_in[5];
    const float* b_a     = (const float*)d_in[6];
    float* out = (float*)d_out;

    const int smem_bytes = (128*WS + 64*XS + 128 + 64) * (int)sizeof(float) + 2*64*4;
    cudaFuncSetAttribute(gates_kernel,
                         cudaFuncAttributeMaxDynamicSharedMemorySize, smem_bytes);

    clear_flags<<<1, 256>>>();
    gates_kernel<<<dim3(GRIDX, H_, 2), 256, smem_bytes>>>(x, segp, a_param,
                                                          w_in, b_in, w_a, b_a);
    fused_scan<<<dim3(W_/256, NCH, B_), 256>>>(out);
}

// round 10
// speedup vs baseline: 2.4170x; 1.4139x over previous
#include <cuda_runtime.h>
#include <cstdint>

// Problem constants
#define B_  4
#define T_  4096
#define W_  1024
#define H_  8

// Fused tiling: block = (chunk of 64 timesteps) x (1 head = 128 ch x 2 gates)
#define CL  64
#define NCH (T_/CL)        // 64 chunks
#define XS  132            // x_s row stride (floats): A-frag bank 4*lr+lc, conflict-free
#define AXS 130            // anx row stride (float2)

// Device scratch (no allocations allowed)
__device__ float2             g_wp2[(size_t)H_*16*4*256];        // packed tf32 weight pairs, 1 MB
__device__ unsigned long long g_agg[(size_t)B_*H_*NCH*128];      // per-chunk (A,H) packed, 2 MB
// layout g_wp2[((h*16+ks)*4+lc)*256 + n] = (w[k0+lc][n], w[k0+lc+4][n]), n = 2*ch+gate

// ---------------- helpers ----------------
__device__ __forceinline__ uint32_t f2tf32(float f) {
    uint32_t r; asm("cvt.rna.tf32.f32 %0, %1;" : "=r"(r) : "f"(f)); return r;
}
__device__ __forceinline__ void mma_tf32(float4 &d, const uint32_t a[4],
                                         uint32_t b0, uint32_t b1) {
    asm("mma.sync.aligned.m16n8k8.row.col.f32.tf32.tf32.f32 "
        "{%0,%1,%2,%3}, {%4,%5,%6,%7}, {%8,%9}, {%0,%1,%2,%3};"
        : "+f"(d.x), "+f"(d.y), "+f"(d.z), "+f"(d.w)
        : "r"(a[0]), "r"(a[1]), "r"(a[2]), "r"(a[3]), "r"(b0), "r"(b1));
}
__device__ __forceinline__ float fast_tanh(float x) {
    float r; asm("tanh.approx.f32 %0, %1;" : "=f"(r) : "f"(x)); return r;
}
__device__ __forceinline__ float fast_sigmoid(float x) {
    return fmaf(fast_tanh(0.5f * x), 0.5f, 0.5f);
}
__device__ __forceinline__ float fast_sqrt(float x) {
    float r; asm("sqrt.approx.f32 %0, %1;" : "=f"(r) : "f"(x)); return r;
}
__device__ __forceinline__ unsigned long long pack_f2(float a, float b) {
    unsigned long long r;
    asm("mov.b64 %0, {%1, %2};" : "=l"(r) : "r"(__float_as_uint(a)), "r"(__float_as_uint(b)));
    return r;
}

// ---------------- K0: pack weights (tf32 pairs) + init agg sentinels ----------------
__global__ __launch_bounds__(256)
void prep_kernel(const float* __restrict__ w_in, const float* __restrict__ w_a)
{
    const int gid = blockIdx.x * 256 + threadIdx.x;    // grid 128 -> 32768 threads
    #pragma unroll
    for (int e = 0; e < 4; ++e) {
        int idx = e * 32768 + gid;                     // < 131072
        int n   = idx & 255;
        int lc  = (idx >> 8) & 3;
        int ks  = (idx >> 10) & 15;
        int h   = idx >> 14;
        int ch  = n >> 1;
        const float* src = (n & 1) ? w_a : w_in;
        int k0 = ks * 8 + lc;
        float v0 = src[h*16384 + k0*128 + ch];
        float v1 = src[h*16384 + (k0 + 4)*128 + ch];
        float2 o;
        o.x = __uint_as_float(f2tf32(v0));
        o.y = __uint_as_float(f2tf32(v1));
        g_wp2[idx] = o;
    }
    #pragma unroll
    for (int e = 0; e < 8; ++e) {
        int idx = e * 32768 + gid;                     // 262144 agg slots
        g_agg[idx] = pack_f2(-1.0f, 0.0f);             // sentinel: A < 0
    }
}

// ---------------- K1: fused gates GEMM + scan (decoupled lookback) ----------------
// Grid (NCH, H, B) with chunk index fastest-varying -> lookback predecessors
// always have lower blockIdx (scheduling-order guarantee, CUB-style).
__global__ __launch_bounds__(256, 2)
void fused_kernel(const float* __restrict__ x, const int* __restrict__ segp,
                  const float* __restrict__ a_param,
                  const float* __restrict__ b_in, const float* __restrict__ b_a,
                  float* __restrict__ out)
{
    extern __shared__ float smem[];
    float*  x_s    = smem;                       // [64][XS] tf32 bits   33792 B
    float2* anx    = (float2*)(smem + 64*XS);    // [64][AXS]            66560 B
    float*  bias_s = (float*)(anx + 64*AXS);     // [256]
    float*  c_s    = bias_s + 256;               // [128]
    int*    seg_s  = (int*)(c_s + 128);          // [64]

    const int tid = threadIdx.x;
    const int c = blockIdx.x, h = blockIdx.y, b = blockIdx.z;
    const int t0 = c * CL;

    // ---- stage: x chunk (tf32), seg, bias, decay consts ----
    {
        const float* xg = x + ((size_t)(b*T_ + t0)) * W_ + h * 128;
        #pragma unroll
        for (int i = tid; i < 64*32; i += 256) {
            int m = i >> 5, q = i & 31;
            float4 v = *(const float4*)(xg + (size_t)m * W_ + q*4);
            float4 o;
            o.x = __uint_as_float(f2tf32(v.x));
            o.y = __uint_as_float(f2tf32(v.y));
            o.z = __uint_as_float(f2tf32(v.z));
            o.w = __uint_as_float(f2tf32(v.w));
            *(float4*)(x_s + m*XS + q*4) = o;
        }
        if (tid < 64)  seg_s[tid] = segp[b*T_ + t0 + tid];
        if (tid < 256) bias_s[tid] = (tid & 1) ? b_a[h*128 + (tid>>1)]
                                               : b_in[h*128 + (tid>>1)];
        if (tid < 128) c_s[tid] = -8.0f * log1pf(__expf(a_param[h*128 + tid]));
    }
    __syncthreads();

    // ---- MMA: z[64 t][256 n] = x[64][128] * w[128][256] ----
    const int warp = tid >> 5, lane = tid & 31;
    const int wm = (warp >> 2) * 32;          // 0 or 32
    const int wn = (warp & 3) * 64;           // n-base
    const int lr = lane >> 2, lcq = lane & 3;

    float4 acc[2][8];
    #pragma unroll
    for (int mf = 0; mf < 2; ++mf)
        #pragma unroll
        for (int nf = 0; nf < 8; ++nf)
            acc[mf][nf] = make_float4(0.f, 0.f, 0.f, 0.f);

    const float2* wp = g_wp2 + (size_t)h * 16 * 4 * 256;
    #pragma unroll
    for (int ks = 0; ks < 16; ++ks) {
        const int k0 = ks * 8;
        uint32_t a[2][4];
        #pragma unroll
        for (int mf = 0; mf < 2; ++mf) {
            const float* xr = x_s + (wm + mf*16 + lr)*XS + k0 + lcq;
            a[mf][0] = __float_as_uint(xr[0]);
            a[mf][1] = __float_as_uint(xr[8*XS]);
            a[mf][2] = __float_as_uint(xr[4]);
            a[mf][3] = __float_as_uint(xr[8*XS + 4]);
        }
        const float2* wk = wp + (ks*4 + lcq)*256;
        #pragma unroll
        for (int nf = 0; nf < 8; ++nf) {
            float2 bv = __ldg(wk + wn + nf*8 + lr);
            uint32_t b0 = __float_as_uint(bv.x);
            uint32_t b1 = __float_as_uint(bv.y);
            mma_tf32(acc[0][nf], a[0], b0, b1);
            mma_tf32(acc[1][nf], a[1], b0, b1);
        }
    }

    // ---- epilogue: gates -> (a, normed_x) into smem ----
    #pragma unroll
    for (int mf = 0; mf < 2; ++mf) {
        #pragma unroll
        for (int nf = 0; nf < 8; ++nf) {
            const int ch = (warp & 3)*32 + nf*4 + lcq;   // 0..127
            const float bx = bias_s[2*ch];
            const float ba = bias_s[2*ch + 1];
            const float cc = c_s[ch];
            #pragma unroll
            for (int half = 0; half < 2; ++half) {
                const int r = wm + mf*16 + lr + half*8;  // 0..63
                const float zx = (half ? acc[mf][nf].z : acc[mf][nf].x) + bx;
                const float za = (half ? acc[mf][nf].w : acc[mf][nf].y) + ba;
                const float gx = fast_sigmoid(zx);
                const float ga = fast_sigmoid(za);
                const float la = cc * ga;
                const float av = __expf(la);
                const float mult = fast_sqrt(fmaxf(1.0f - av*av, 0.0f));
                const float xv = x_s[r*XS + ch];         // tf32-truncated x
                const float nx = xv * gx * mult;
                const float ao = (seg_s[r] == 0) ? 0.0f : av;
                anx[r*AXS + ch] = make_float2(ao, nx);
            }
        }
    }
    __syncthreads();

    // ---- local chunk summary + publish (single 8B atomic payload) ----
    if (tid < 128) {
        float A = 1.0f, Hl = 0.0f;
        #pragma unroll 8
        for (int t = 0; t < CL; ++t) {
            float2 v = anx[t*AXS + tid];
            Hl = fmaf(v.x, Hl, v.y);
            A *= v.x;
        }
        volatile unsigned long long* dst =
            (volatile unsigned long long*)&g_agg[(((size_t)(b*H_ + h))*NCH + c)*128 + tid];
        *dst = pack_f2(A, Hl);

        // ---- decoupled lookback: compose predecessor aggregates ----
        float carry = 0.0f;
        if (c > 0) {
            const unsigned long long* ag =
                &g_agg[((size_t)(b*H_ + h))*NCH*128 + tid];
            #pragma unroll 1
            for (int k = 0; k < c; ++k) {
                unsigned long long v;
                do {
                    v = *(volatile const unsigned long long*)(ag + (size_t)k*128);
                } while (__uint_as_float((unsigned)(v & 0xffffffffull)) < 0.0f);
                float Ak = __uint_as_float((unsigned)(v & 0xffffffffull));
                float Hk = __uint_as_float((unsigned)(v >> 32));
                carry = fmaf(Ak, carry, Hk);
            }
        }

        // ---- replay with carry, write output ----
        float hh = carry;
        float* og = out + ((size_t)(b*T_ + t0)) * W_ + h*128 + tid;
        #pragma unroll 8
        for (int t = 0; t < CL; ++t) {
            float2 v = anx[t*AXS + tid];
            hh = fmaf(v.x, hh, v.y);
            og[(size_t)t * W_] = hh;
        }
    }
}

// ---------------- launch ----------------
extern "C" void kernel_launch(void* const* d_in, const int* in_sizes, int n_in,
                              void* d_out, int out_size)
{
    const float* x       = (const float*)d_in[0];
    const int*   segp    = (const int*)  d_in[1];
    const float* a_param = (const float*)d_in[2];
    const float* w_in    = (const float*)d_in[3];
    const float* b_in    = (const float*)d_in[4];
    const float* w_a     = (const float*)d_in[5];
    const float* b_a     = (const float*)d_in[6];
    float* out = (float*)d_out;

    const int smem_bytes = 64*XS*4 + 64*AXS*8 + 256*4 + 128*4 + 64*4;  // 102144
    cudaFuncSetAttribute(fused_kernel,
                         cudaFuncAttributeMaxDynamicSharedMemorySize, smem_bytes);

    prep_kernel<<<128, 256>>>(w_in, w_a);
    fused_kernel<<<dim3(NCH, H_, B_), 256, smem_bytes>>>(x, segp, a_param,
                                                         b_in, b_a, out);
}

// round 13
// speedup vs baseline: 2.7205x; 1.1256x over previous
#include <cuda_runtime.h>
#include <cstdint>

// Problem constants
#define B_  4
#define T_  4096
#define W_  1024
#define H_  8

// Fused tiling: block = (chunk of 64 timesteps) x (1 head = 128 ch x 2 gates)
#define CL  64
#define NCH (T_/CL)        // 64 chunks
#define XS  132            // x_s row stride (floats): A-frag bank 4*lr+lc, conflict-free
#define AXS 130            // anx row stride (float2)

typedef unsigned long long ull;

// Device scratch (no allocations allowed)
__device__ float2 g_wp2[(size_t)H_*16*4*256];     // packed tf32 weight pairs, 1 MB
__device__ ull    g_loc[(size_t)B_*H_*NCH*128];   // per-chunk local (P_full, L_full)
__device__ ull    g_inc[(size_t)B_*H_*NCH*128];   // per-chunk inclusive (flag, h_incl)

// ---------------- helpers ----------------
__device__ __forceinline__ uint32_t f2tf32(float f) {
    uint32_t r; asm("cvt.rna.tf32.f32 %0, %1;" : "=r"(r) : "f"(f)); return r;
}
__device__ __forceinline__ void mma_tf32(float4 &d, const uint32_t a[4],
                                         uint32_t b0, uint32_t b1) {
    asm("mma.sync.aligned.m16n8k8.row.col.f32.tf32.tf32.f32 "
        "{%0,%1,%2,%3}, {%4,%5,%6,%7}, {%8,%9}, {%0,%1,%2,%3};"
        : "+f"(d.x), "+f"(d.y), "+f"(d.z), "+f"(d.w)
        : "r"(a[0]), "r"(a[1]), "r"(a[2]), "r"(a[3]), "r"(b0), "r"(b1));
}
__device__ __forceinline__ float fast_tanh(float x) {
    float r; asm("tanh.approx.f32 %0, %1;" : "=f"(r) : "f"(x)); return r;
}
__device__ __forceinline__ float fast_sigmoid(float x) {
    return fmaf(fast_tanh(0.5f * x), 0.5f, 0.5f);
}
__device__ __forceinline__ float fast_sqrt(float x) {
    float r; asm("sqrt.approx.f32 %0, %1;" : "=f"(r) : "f"(x)); return r;
}
__device__ __forceinline__ ull pack_f2(float a, float b) {
    ull r;
    asm("mov.b64 %0, {%1, %2};" : "=l"(r) : "r"(__float_as_uint(a)), "r"(__float_as_uint(b)));
    return r;
}
__device__ __forceinline__ float lo_f(ull v) { return __uint_as_float((unsigned)(v & 0xffffffffull)); }
__device__ __forceinline__ float hi_f(ull v) { return __uint_as_float((unsigned)(v >> 32)); }

// ---------------- K0: pack weights (tf32 pairs) + init sentinels ----------------
__global__ __launch_bounds__(256)
void prep_kernel(const float* __restrict__ w_in, const float* __restrict__ w_a)
{
    const int gid = blockIdx.x * 256 + threadIdx.x;    // grid 128 -> 32768 threads
    #pragma unroll
    for (int e = 0; e < 4; ++e) {
        int idx = e * 32768 + gid;                     // < 131072
        int n   = idx & 255;
        int lc  = (idx >> 8) & 3;
        int ks  = (idx >> 10) & 15;
        int h   = idx >> 14;
        int ch  = n >> 1;
        const float* src = (n & 1) ? w_a : w_in;
        int k0 = ks * 8 + lc;
        float v0 = src[h*16384 + k0*128 + ch];
        float v1 = src[h*16384 + (k0 + 4)*128 + ch];
        float2 o;
        o.x = __uint_as_float(f2tf32(v0));
        o.y = __uint_as_float(f2tf32(v1));
        g_wp2[idx] = o;
    }
    const ull sent = pack_f2(-1.0f, 0.0f);
    #pragma unroll
    for (int e = 0; e < 8; ++e) {
        int idx = e * 32768 + gid;                     // 262144 slots each
        g_loc[idx] = sent;
        g_inc[idx] = sent;
    }
}

// ---------------- K1: fused gates GEMM + scan (two-flag decoupled lookback) ----------------
// Grid (NCH, H, B), chunk index fastest -> lookback predecessors have lower bid.
__global__ __launch_bounds__(256, 2)
void fused_kernel(const float* __restrict__ x, const int* __restrict__ segp,
                  const float* __restrict__ a_param,
                  const float* __restrict__ b_in, const float* __restrict__ b_a,
                  float* __restrict__ out)
{
    extern __shared__ float smem[];
    float*  x_s     = smem;                       // [64][XS] tf32 bits   33792 B
    float2* anx     = (float2*)(smem + 64*XS);    // [64][AXS] -> (P,L)   66560 B
    float*  bias_s  = (float*)(anx + 64*AXS);     // [256]
    float*  c_s     = bias_s + 256;               // [128]
    float*  carry_s = c_s + 128;                  // [128]
    int*    seg_s   = (int*)(carry_s + 128);      // [64]

    const int tid = threadIdx.x;
    const int c = blockIdx.x, h = blockIdx.y, b = blockIdx.z;
    const int t0 = c * CL;
    const int bh = b * H_ + h;

    // ---- stage: x chunk (tf32), seg, bias, decay consts ----
    {
        const float* xg = x + ((size_t)(b*T_ + t0)) * W_ + h * 128;
        #pragma unroll
        for (int i = tid; i < 64*32; i += 256) {
            int m = i >> 5, q = i & 31;
            float4 v = *(const float4*)(xg + (size_t)m * W_ + q*4);
            float4 o;
            o.x = __uint_as_float(f2tf32(v.x));
            o.y = __uint_as_float(f2tf32(v.y));
            o.z = __uint_as_float(f2tf32(v.z));
            o.w = __uint_as_float(f2tf32(v.w));
            *(float4*)(x_s + m*XS + q*4) = o;
        }
        if (tid < 64)  seg_s[tid] = segp[b*T_ + t0 + tid];
        if (tid < 256) bias_s[tid] = (tid & 1) ? b_a[h*128 + (tid>>1)]
                                               : b_in[h*128 + (tid>>1)];
        if (tid < 128) c_s[tid] = -8.0f * log1pf(__expf(a_param[h*128 + tid]));
    }
    __syncthreads();

    // ---- MMA: z[64 t][256 n] = x[64][128] * w[128][256] ----
    const int warp = tid >> 5, lane = tid & 31;
    const int wm = (warp >> 2) * 32;
    const int wn = (warp & 3) * 64;
    const int lr = lane >> 2, lcq = lane & 3;

    float4 acc[2][8];
    #pragma unroll
    for (int mf = 0; mf < 2; ++mf)
        #pragma unroll
        for (int nf = 0; nf < 8; ++nf)
            acc[mf][nf] = make_float4(0.f, 0.f, 0.f, 0.f);

    const float2* wp = g_wp2 + (size_t)h * 16 * 4 * 256;
    #pragma unroll
    for (int ks = 0; ks < 16; ++ks) {
        const int k0 = ks * 8;
        uint32_t a[2][4];
        #pragma unroll
        for (int mf = 0; mf < 2; ++mf) {
            const float* xr = x_s + (wm + mf*16 + lr)*XS + k0 + lcq;
            a[mf][0] = __float_as_uint(xr[0]);
            a[mf][1] = __float_as_uint(xr[8*XS]);
            a[mf][2] = __float_as_uint(xr[4]);
            a[mf][3] = __float_as_uint(xr[8*XS + 4]);
        }
        const float2* wk = wp + (ks*4 + lcq)*256;
        #pragma unroll
        for (int nf = 0; nf < 8; ++nf) {
            float2 bv = __ldg(wk + wn + nf*8 + lr);
            uint32_t b0 = __float_as_uint(bv.x);
            uint32_t b1 = __float_as_uint(bv.y);
            mma_tf32(acc[0][nf], a[0], b0, b1);
            mma_tf32(acc[1][nf], a[1], b0, b1);
        }
    }

    // ---- epilogue: gates -> (a, normed_x) into smem ----
    #pragma unroll
    for (int mf = 0; mf < 2; ++mf) {
        #pragma unroll
        for (int nf = 0; nf < 8; ++nf) {
            const int ch = (warp & 3)*32 + nf*4 + lcq;
            const float bx = bias_s[2*ch];
            const float ba = bias_s[2*ch + 1];
            const float cc = c_s[ch];
            #pragma unroll
            for (int half = 0; half < 2; ++half) {
                const int r = wm + mf*16 + lr + half*8;
                const float zx = (half ? acc[mf][nf].z : acc[mf][nf].x) + bx;
                const float za = (half ? acc[mf][nf].w : acc[mf][nf].y) + ba;
                const float gx = fast_sigmoid(zx);
                const float ga = fast_sigmoid(za);
                const float la = cc * ga;
                const float av = __expf(la);
                const float mult = fast_sqrt(fmaxf(1.0f - av*av, 0.0f));
                const float xv = x_s[r*XS + ch];
                const float nx = xv * gx * mult;
                const float ao = (seg_s[r] == 0) ? 0.0f : av;
                anx[r*AXS + ch] = make_float2(ao, nx);
            }
        }
    }
    __syncthreads();

    // ---- summary: convert (a,nx) -> running (P,L) in place; publish; lookback ----
    if (tid < 128) {
        float P = 1.0f, L = 0.0f;
        #pragma unroll 8
        for (int t = 0; t < CL; ++t) {
            float2 v = anx[t*AXS + tid];
            L = fmaf(v.x, L, v.y);
            P *= v.x;
            anx[t*AXS + tid] = make_float2(P, L);
        }
        const size_t slot = ((size_t)bh * NCH + c) * 128 + tid;
        *(volatile ull*)&g_loc[slot] = pack_f2(P, L);   // publish local ASAP

        // two-flag decoupled lookback
        float carry = 0.0f;
        if (c > 0) {
            float Aacc = 1.0f, Hacc = 0.0f;
            int k = c - 1;
            const ull* incp = g_inc + (size_t)bh * NCH * 128 + tid;
            const ull* locp = g_loc + (size_t)bh * NCH * 128 + tid;
            while (true) {
                ull v = *(volatile const ull*)(incp + (size_t)k * 128);
                if (lo_f(v) >= 0.0f) {                  // inclusive available: stop
                    carry = fmaf(Aacc, hi_f(v), Hacc);
                    break;
                }
                ull w = *(volatile const ull*)(locp + (size_t)k * 128);
                float Pk = lo_f(w);
                if (Pk >= 0.0f) {                       // local available: compose, step back
                    Hacc = fmaf(Aacc, hi_f(w), Hacc);
                    Aacc *= Pk;
                    if (--k < 0) { carry = Hacc; break; }
                }
            }
        }
        // publish inclusive state for this chunk
        *(volatile ull*)&g_inc[slot] = pack_f2(1.0f, fmaf(P, carry, L));
        carry_s[tid] = carry;
    }
    __syncthreads();

    // ---- parallel output: out(t,ch) = P(t,ch)*carry(ch) + L(t,ch), all 256 thr ----
    {
        float* og = out + ((size_t)(b*T_ + t0)) * W_ + h * 128;
        #pragma unroll
        for (int j = 0; j < 8; ++j) {
            int i  = tid + j * 256;          // 0..2047 float4 groups
            int t  = i >> 5;
            int c4 = (i & 31) * 4;
            float4 pl01 = *(const float4*)(&anx[t*AXS + c4]);      // (P0,L0,P1,L1)
            float4 pl23 = *(const float4*)(&anx[t*AXS + c4 + 2]);  // (P2,L2,P3,L3)
            float4 o;
            o.x = fmaf(pl01.x, carry_s[c4],     pl01.y);
            o.y = fmaf(pl01.z, carry_s[c4 + 1], pl01.w);
            o.z = fmaf(pl23.x, carry_s[c4 + 2], pl23.y);
            o.w = fmaf(pl23.z, carry_s[c4 + 3], pl23.w);
            *(float4*)(og + (size_t)t * W_ + c4) = o;
        }
    }
}

// ---------------- launch ----------------
extern "C" void kernel_launch(void* const* d_in, const int* in_sizes, int n_in,
                              void* d_out, int out_size)
{
    const float* x       = (const float*)d_in[0];
    const int*   segp    = (const int*)  d_in[1];
    const float* a_param = (const float*)d_in[2];
    const float* w_in    = (const float*)d_in[3];
    const float* b_in    = (const float*)d_in[4];
    const float* w_a     = (const float*)d_in[5];
    const float* b_a     = (const float*)d_in[6];
    float* out = (float*)d_out;

    const int smem_bytes = 64*XS*4 + 64*AXS*8 + 256*4 + 128*4 + 128*4 + 64*4;  // 102656
    cudaFuncSetAttribute(fused_kernel,
                         cudaFuncAttributeMaxDynamicSharedMemorySize, smem_bytes);

    prep_kernel<<<128, 256>>>(w_in, w_a);
    fused_kernel<<<dim3(NCH, H_, B_), 256, smem_bytes>>>(x, segp, a_param,
                                                         b_in, b_a, out);
}